// round 7
// baseline (speedup 1.0000x reference)
#include <cuda_runtime.h>
#include <cuda_fp16.h>
#include <math.h>
#include <stdint.h>

// ---------------- problem constants ----------------
#define SN_     32
#define NROI    512
#define NCH     480
#define TFRM    4
#define FY      45
#define FX      80
#define OSZ     7
#define DIN     23520
#define NDF     1024
#define NCLUS   50
#define KTOT    23520
#define KPAD    23552          // 736 k-tiles of 32
#define SPLITK  16
#define KT_PER  46             // 736 / 16 k-tiles per split chunk
#define NT_PER  138            // 3 phases * 46

// GEMM tiling
#define BM 128
#define BN 128
#define BK 32                  // fp16 elems per k-tile (64B rows)
#define SROW 80                // 64B data + 16B pad (conflict-free ldsm)
#define SUBT_B (BM * SROW)     // 10240 per sub-tile
#define STAGE_B (2 * SUBT_B)   // A + B = 20480
#define NSTAGE 4
#define SMEM_DYN (NSTAGE * STAGE_B)   // 81920 -> 2 CTAs/SM

// ---------------- scratch ----------------
__device__ __align__(128) __half g_pl_hi[(size_t)NROI * KPAD];   // 24 MB
__device__ __align__(128) __half g_pl_lo[(size_t)NROI * KPAD];   // 24 MB
__device__ __align__(128) __half g_w_hi [(size_t)NDF  * KPAD];   // 48 MB
__device__ __align__(128) __half g_w_lo [(size_t)NDF  * KPAD];   // 48 MB
__device__ float g_partial[(size_t)SPLITK * NROI * NDF];         // 32 MB

// ---------------- helpers ----------------
__device__ __forceinline__ uint32_t smem_u32(const void* p) {
    uint32_t a;
    asm("{ .reg .u64 t; cvta.to.shared.u64 t, %1; cvt.u32.u64 %0, t; }" : "=r"(a) : "l"(p));
    return a;
}
__device__ __forceinline__ void cp_async16(uint32_t dst, const void* src) {
    asm volatile("cp.async.cg.shared.global [%0], [%1], 16;" :: "r"(dst), "l"(src) : "memory");
}
__device__ __forceinline__ void cp_commit() {
    asm volatile("cp.async.commit_group;" ::: "memory");
}
template <int N>
__device__ __forceinline__ void cp_wait() {
    asm volatile("cp.async.wait_group %0;" :: "n"(N) : "memory");
}
__device__ __forceinline__ void ldsm_x4(uint32_t* r, uint32_t addr) {
    asm volatile("ldmatrix.sync.aligned.m8n8.x4.shared.b16 {%0,%1,%2,%3}, [%4];"
                 : "=r"(r[0]), "=r"(r[1]), "=r"(r[2]), "=r"(r[3]) : "r"(addr));
}
__device__ __forceinline__ void mma_f16(float* c, const uint32_t* a, uint32_t b0, uint32_t b1) {
    asm volatile(
        "mma.sync.aligned.m16n8k16.row.col.f32.f16.f16.f32 "
        "{%0,%1,%2,%3}, {%4,%5,%6,%7}, {%8,%9}, {%0,%1,%2,%3};"
        : "+f"(c[0]), "+f"(c[1]), "+f"(c[2]), "+f"(c[3])
        : "r"(a[0]), "r"(a[1]), "r"(a[2]), "r"(a[3]), "r"(b0), "r"(b1));
}
__device__ __forceinline__ float nan_to_num(float v) {
    if (isnan(v)) return 0.0f;
    if (isinf(v)) return v > 0.0f ? 3.4028234663852886e38f : -3.4028234663852886e38f;
    return v;
}

// ---------------- kernel 1: RoI align -> fp16 hi/lo pooled ----------------
__global__ void roi_pool_kernel(const float* __restrict__ zvis,
                                const float* __restrict__ bboxs) {
    __shared__ int   s_off[49][4];
    __shared__ float s_w[49][4];

    const int r   = blockIdx.x;
    const int b   = r / SN_;
    const int tid = threadIdx.x;

    if (tid < 49) {
        const float* bb = bboxs + (size_t)r * 4;
        const float sc = 0.0625f;
        float x1 = nan_to_num(bb[0] * sc) - 0.5f;
        float y1 = nan_to_num(bb[1] * sc) - 0.5f;
        float x2 = nan_to_num(bb[2] * sc) - 0.5f;
        float y2 = nan_to_num(bb[3] * sc) - 0.5f;
        float bw = (x2 - x1) * (1.0f / OSZ);
        float bh = (y2 - y1) * (1.0f / OSZ);

        int py = tid / OSZ, px = tid - py * OSZ;
        float y = y1 + ((float)py + 0.5f) * bh;
        float x = x1 + ((float)px + 0.5f) * bw;
        bool valid = (y > -1.0f) && (y < (float)FY) && (x > -1.0f) && (x < (float)FX);
        float yc = fminf(fmaxf(y, 0.0f), (float)(FY - 1));
        float xc = fminf(fmaxf(x, 0.0f), (float)(FX - 1));
        int yl = (int)floorf(yc);
        int xl = (int)floorf(xc);
        int yh = min(yl + 1, FY - 1);
        int xh = min(xl + 1, FX - 1);
        float ly = yc - (float)yl, lx = xc - (float)xl;
        float hy = 1.0f - ly, hx = 1.0f - lx;
        float vm = valid ? 1.0f : 0.0f;

        s_off[tid][0] = yl * FX + xl;
        s_off[tid][1] = yl * FX + xh;
        s_off[tid][2] = yh * FX + xl;
        s_off[tid][3] = yh * FX + xh;
        s_w[tid][0] = hy * hx * vm;
        s_w[tid][1] = hy * lx * vm;
        s_w[tid][2] = ly * hx * vm;
        s_w[tid][3] = ly * lx * vm;
    }
    __syncthreads();

    const float* fbase = zvis + (size_t)b * NCH * TFRM * FY * FX + (size_t)3 * FY * FX;
    __half* ohi = g_pl_hi + (size_t)r * KPAD;
    __half* olo = g_pl_lo + (size_t)r * KPAD;

    for (int k = tid; k < DIN; k += 256) {
        int c = k / 49;
        int p = k - c * 49;
        const float* f = fbase + (size_t)c * (TFRM * FY * FX);
        float v = s_w[p][0] * f[s_off[p][0]]
                + s_w[p][1] * f[s_off[p][1]]
                + s_w[p][2] * f[s_off[p][2]]
                + s_w[p][3] * f[s_off[p][3]];
        __half h = __float2half_rn(v);
        ohi[k] = h;
        olo[k] = __float2half_rn(v - __half2float(h));
    }
    if (tid < (KPAD - DIN)) {
        ohi[DIN + tid] = __float2half_rn(0.0f);
        olo[DIN + tid] = __float2half_rn(0.0f);
    }
}

// ---------------- kernel 1b: convert w_vis f32 -> fp16 hi/lo ----------------
__global__ void convert_w_kernel(const float* __restrict__ Wv) {
    const int row = blockIdx.x;
    const int tid = threadIdx.x;
    const float* src = Wv + (size_t)row * KTOT;
    uint2* dhi = (uint2*)(g_w_hi + (size_t)row * KPAD);
    uint2* dlo = (uint2*)(g_w_lo + (size_t)row * KPAD);

    for (int k4 = tid; k4 < KPAD / 4; k4 += 256) {
        int k = k4 * 4;
        uint2 hi, lo;
        if (k < KTOT) {
            float4 v = *(const float4*)(src + k);
            __half2 h0 = __floats2half2_rn(v.x, v.y);
            __half2 h1 = __floats2half2_rn(v.z, v.w);
            float2 f0 = __half22float2(h0);
            float2 f1 = __half22float2(h1);
            __half2 l0 = __floats2half2_rn(v.x - f0.x, v.y - f0.y);
            __half2 l1 = __floats2half2_rn(v.z - f1.x, v.w - f1.y);
            hi = make_uint2(*(uint32_t*)&h0, *(uint32_t*)&h1);
            lo = make_uint2(*(uint32_t*)&l0, *(uint32_t*)&l1);
        } else {
            hi = make_uint2(0, 0);
            lo = make_uint2(0, 0);
        }
        dhi[k4] = hi;
        dlo[k4] = lo;
    }
}

// ---------------- kernel 2: fp16 three-term HMMA GEMM, phase-major stream ----------------
// tile stream per CTA: t in [0,138): phase0 Ah*Bh (t<46), phase1 Al*Bh, phase2 Ah*Bl
__global__ void __launch_bounds__(256, 2) gemm_hmma(int) {
    extern __shared__ __align__(16) char smem[];

    const int tid   = threadIdx.x;
    const int warp  = tid >> 5;
    const int lane  = tid & 31;
    const int nBase = blockIdx.x * BN;
    const int mBase = blockIdx.y * BM;
    const int z     = blockIdx.z;

    const uint32_t sbase = smem_u32(smem);

    // loader mapping
    const int lrow = tid >> 2;        // 0..63
    const int lseg = tid & 3;         // 16B segment

    // compute mapping
    const int warpM = warp >> 2;      // 0..1 -> *64
    const int warpN = warp & 3;       // 0..3 -> *32
    const uint32_t a_row = (uint32_t)(warpM * 64 + (lane & 15));
    const uint32_t a_seg = (uint32_t)(lane >> 4);
    const uint32_t b_row = (uint32_t)(warpN * 32 + ((lane >> 4) << 3) + (lane & 7));
    const uint32_t b_seg = (uint32_t)((lane >> 3) & 1);

    float acc[4][4][4];
    #pragma unroll
    for (int i = 0; i < 4; ++i)
        #pragma unroll
        for (int j = 0; j < 4; ++j)
            #pragma unroll
            for (int q = 0; q < 4; ++q) acc[i][j][q] = 0.0f;

    auto load_stage = [&](int s, int t) {
        const int ph = (t >= 2 * KT_PER) ? 2 : ((t >= KT_PER) ? 1 : 0);
        const int kk = t - ph * KT_PER;
        const int koff = (z * KT_PER + kk) * BK;
        const __half* aS = (ph == 1) ? g_pl_lo : g_pl_hi;
        const __half* bS = (ph == 2) ? g_w_lo : g_w_hi;
        const uint32_t st = sbase + s * STAGE_B;
        const __half* a0 = aS + (size_t)(mBase + lrow)      * KPAD + koff + lseg * 8;
        const __half* a1 = aS + (size_t)(mBase + lrow + 64) * KPAD + koff + lseg * 8;
        const __half* b0 = bS + (size_t)(nBase + lrow)      * KPAD + koff + lseg * 8;
        const __half* b1 = bS + (size_t)(nBase + lrow + 64) * KPAD + koff + lseg * 8;
        cp_async16(st +          lrow * SROW        + lseg * 16, a0);
        cp_async16(st +         (lrow + 64) * SROW  + lseg * 16, a1);
        cp_async16(st + SUBT_B + lrow * SROW        + lseg * 16, b0);
        cp_async16(st + SUBT_B + (lrow + 64) * SROW + lseg * 16, b1);
        cp_commit();
    };

    load_stage(0, 0);
    load_stage(1, 1);
    load_stage(2, 2);

    for (int t = 0; t < NT_PER; ++t) {
        cp_wait<2>();
        __syncthreads();
        if (t + 3 < NT_PER) load_stage((t + 3) & 3, t + 3);

        const uint32_t sa = sbase + (t & 3) * STAGE_B;
        const uint32_t sb = sa + SUBT_B;

        #pragma unroll
        for (int ks = 0; ks < 2; ++ks) {
            uint32_t b[2][4];
            #pragma unroll
            for (int pr = 0; pr < 2; ++pr)
                ldsm_x4(b[pr], sb + (b_row + pr * 16) * SROW + (ks * 2 + b_seg) * 16);

            uint32_t a[4][4];
            #pragma unroll
            for (int mf = 0; mf < 4; ++mf)
                ldsm_x4(a[mf], sa + (a_row + mf * 16) * SROW + (ks * 2 + a_seg) * 16);

            #pragma unroll
            for (int mf = 0; mf < 4; ++mf)
                #pragma unroll
                for (int nf = 0; nf < 4; ++nf)
                    mma_f16(acc[mf][nf], a[mf], b[nf >> 1][(nf & 1) * 2], b[nf >> 1][(nf & 1) * 2 + 1]);
        }
    }

    // epilogue -> g_partial[z][m][n]
    const int group = lane >> 2;
    const int quad  = lane & 3;
    #pragma unroll
    for (int mf = 0; mf < 4; ++mf) {
        int row0 = mBase + warpM * 64 + mf * 16 + group;
        #pragma unroll
        for (int nf = 0; nf < 4; ++nf) {
            int col = nBase + warpN * 32 + nf * 8 + quad * 2;
            float* p0 = g_partial + ((size_t)z * NROI + row0) * NDF + col;
            float* p1 = p0 + (size_t)8 * NDF;
            *(float2*)p0 = make_float2(acc[mf][nf][0], acc[mf][nf][1]);
            *(float2*)p1 = make_float2(acc[mf][nf][2], acc[mf][nf][3]);
        }
    }
}

// ---------------- kernel 3: fused reduce + bias + cluster (2 rois/block) ----------------
__global__ void cluster_fused_kernel(const float* __restrict__ norms,
                                     const float* __restrict__ b_vis,
                                     const float* __restrict__ w_spc,
                                     const float* __restrict__ b_spc,
                                     const float* __restrict__ cent,
                                     float* __restrict__ Z,
                                     float* __restrict__ out_s,
                                     float* __restrict__ out_c) {
    __shared__ __align__(16) float zrow[2][NDF];
    __shared__ float sdist[2][NCLUS];
    __shared__ float ssum[2];
    __shared__ int   sarg[2];

    const int m0  = blockIdx.x * 2;
    const int tid = threadIdx.x;
    const float nm0 = norms[m0];
    const float nm1 = norms[m0 + 1];

    for (int d = tid; d < NDF; d += 256) {
        float base = b_vis[d] + b_spc[d];
        float w = w_spc[d];
        float a0 = base + nm0 * w;
        float a1 = base + nm1 * w;
        #pragma unroll
        for (int zz = 0; zz < SPLITK; ++zz) {
            a0 += g_partial[((size_t)zz * NROI + m0) * NDF + d];
            a1 += g_partial[((size_t)zz * NROI + m0 + 1) * NDF + d];
        }
        zrow[0][d] = a0;  Z[(size_t)m0 * NDF + d] = a0;
        zrow[1][d] = a1;  Z[(size_t)(m0 + 1) * NDF + d] = a1;
    }
    __syncthreads();

    const int warp = tid >> 5;
    const int lane = tid & 31;
    for (int k = warp; k < NCLUS; k += 8) {
        const float4* ck = (const float4*)(cent + (size_t)k * NDF);
        float s0 = 0.0f, s1 = 0.0f;
        #pragma unroll
        for (int i = 0; i < 8; ++i) {
            int d4 = i * 32 + lane;
            float4 c  = ck[d4];
            float4 z0 = *(const float4*)&zrow[0][d4 * 4];
            float4 z1 = *(const float4*)&zrow[1][d4 * 4];
            float t;
            t = z0.x - c.x; s0 += t * t;  t = z0.y - c.y; s0 += t * t;
            t = z0.z - c.z; s0 += t * t;  t = z0.w - c.w; s0 += t * t;
            t = z1.x - c.x; s1 += t * t;  t = z1.y - c.y; s1 += t * t;
            t = z1.z - c.z; s1 += t * t;  t = z1.w - c.w; s1 += t * t;
        }
        #pragma unroll
        for (int o = 16; o; o >>= 1) {
            s0 += __shfl_xor_sync(0xffffffffu, s0, o);
            s1 += __shfl_xor_sync(0xffffffffu, s1, o);
        }
        if (lane == 0) { sdist[0][k] = sqrtf(s0); sdist[1][k] = sqrtf(s1); }
    }
    __syncthreads();

    if (tid < 2) {
        float sum = 0.0f, best = -1.0f;
        int bi = 0;
        for (int k = 0; k < NCLUS; ++k) {
            float st = 1.0f / (1.0f + sdist[tid][k]);
            sum += st;
            if (st > best) { best = st; bi = k; }
        }
        ssum[tid] = sum;
        sarg[tid] = bi;
    }
    __syncthreads();

    if (tid < NCLUS)
        out_s[(size_t)m0 * NCLUS + tid] = (1.0f / (1.0f + sdist[0][tid])) / ssum[0];
    else if (tid >= 64 && tid < 64 + NCLUS)
        out_s[(size_t)(m0 + 1) * NCLUS + (tid - 64)] = (1.0f / (1.0f + sdist[1][tid - 64])) / ssum[1];
    if (tid == 0) out_c[m0] = (float)sarg[0];
    if (tid == 1) out_c[m0 + 1] = (float)sarg[1];
}

// ---------------- launch ----------------
extern "C" void kernel_launch(void* const* d_in, const int* in_sizes, int n_in,
                              void* d_out, int out_size) {
    const float* z_vis     = (const float*)d_in[0];
    const float* bboxs     = (const float*)d_in[1];
    const float* norms     = (const float*)d_in[2];
    const float* w_vis     = (const float*)d_in[3];
    const float* b_vis     = (const float*)d_in[4];
    const float* w_spc     = (const float*)d_in[5];
    const float* b_spc     = (const float*)d_in[6];
    const float* centroids = (const float*)d_in[7];

    float* out = (float*)d_out;
    float* Z = out;
    float* S = out + (size_t)NROI * NDF;
    float* C = S + (size_t)NROI * NCLUS;

    cudaFuncSetAttribute(gemm_hmma, cudaFuncAttributeMaxDynamicSharedMemorySize, SMEM_DYN);

    roi_pool_kernel<<<NROI, 256>>>(z_vis, bboxs);
    convert_w_kernel<<<NDF, 256>>>(w_vis);

    dim3 gg(NDF / BN, NROI / BM, SPLITK);        // (8, 4, 16) = 512 CTAs
    gemm_hmma<<<gg, 256, SMEM_DYN>>>(0);

    cluster_fused_kernel<<<NROI / 2, 256>>>(norms, b_vis, w_spc, b_spc, centroids, Z, S, C);
}

// round 8
// speedup vs baseline: 1.1710x; 1.1710x over previous
#include <cuda_runtime.h>
#include <cuda_fp16.h>
#include <math.h>
#include <stdint.h>

// ---------------- problem constants ----------------
#define SN_     32
#define NROI    512
#define NCH     480
#define TFRM    4
#define FY      45
#define FX      80
#define OSZ     7
#define DIN     23520
#define NDF     1024
#define NCLUS   50
#define KTOT    23520
#define KPAD    23552          // 736 k-tiles of 32
#define SPLITK  23
#define KT_PER  32             // 736 / 23

// GEMM tiling
#define BM 128
#define BN 128
#define BK 32                  // fp16 elems per k-tile (64B rows)
#define SROW 80                // 64B data + 16B pad (conflict-free ldsm)
#define SUBT_B (BM * SROW)     // 10240 per sub-tile
#define STAGE_B (4 * SUBT_B)   // Ah + Al + Bh + Bl = 40960
#define NSTAGE 5
#define SMEM_DYN (NSTAGE * STAGE_B)   // 204800

// ---------------- scratch ----------------
__device__ __align__(128) __half g_pl_hi[(size_t)NROI * KPAD];   // 24 MB
__device__ __align__(128) __half g_pl_lo[(size_t)NROI * KPAD];   // 24 MB
__device__ __align__(128) __half g_w_hi [(size_t)NDF  * KPAD];   // 48 MB
__device__ __align__(128) __half g_w_lo [(size_t)NDF  * KPAD];   // 48 MB
__device__ float g_partial[(size_t)SPLITK * NROI * NDF];         // 48 MB

// ---------------- helpers ----------------
__device__ __forceinline__ uint32_t smem_u32(const void* p) {
    uint32_t a;
    asm("{ .reg .u64 t; cvta.to.shared.u64 t, %1; cvt.u32.u64 %0, t; }" : "=r"(a) : "l"(p));
    return a;
}
__device__ __forceinline__ void cp_async16(uint32_t dst, const void* src) {
    asm volatile("cp.async.cg.shared.global [%0], [%1], 16;" :: "r"(dst), "l"(src) : "memory");
}
__device__ __forceinline__ void cp_commit() {
    asm volatile("cp.async.commit_group;" ::: "memory");
}
template <int N>
__device__ __forceinline__ void cp_wait() {
    asm volatile("cp.async.wait_group %0;" :: "n"(N) : "memory");
}
__device__ __forceinline__ void ldsm_x4(uint32_t* r, uint32_t addr) {
    asm volatile("ldmatrix.sync.aligned.m8n8.x4.shared.b16 {%0,%1,%2,%3}, [%4];"
                 : "=r"(r[0]), "=r"(r[1]), "=r"(r[2]), "=r"(r[3]) : "r"(addr));
}
__device__ __forceinline__ void mma_f16(float* c, const uint32_t* a, uint32_t b0, uint32_t b1) {
    asm volatile(
        "mma.sync.aligned.m16n8k16.row.col.f32.f16.f16.f32 "
        "{%0,%1,%2,%3}, {%4,%5,%6,%7}, {%8,%9}, {%0,%1,%2,%3};"
        : "+f"(c[0]), "+f"(c[1]), "+f"(c[2]), "+f"(c[3])
        : "r"(a[0]), "r"(a[1]), "r"(a[2]), "r"(a[3]), "r"(b0), "r"(b1));
}
__device__ __forceinline__ float nan_to_num(float v) {
    if (isnan(v)) return 0.0f;
    if (isinf(v)) return v > 0.0f ? 3.4028234663852886e38f : -3.4028234663852886e38f;
    return v;
}

// ---------------- kernel 1: fused producers ----------------
// blocks [0, NROI): RoI-align -> pooled hi/lo fp16
// blocks [NROI, NROI+NDF): w_vis row -> w hi/lo fp16
__global__ void producers_kernel(const float* __restrict__ zvis,
                                 const float* __restrict__ bboxs,
                                 const float* __restrict__ Wv) {
    const int bid = blockIdx.x;
    const int tid = threadIdx.x;

    if (bid >= NROI) {
        // ---- w_vis conversion path ----
        const int row = bid - NROI;
        const float* src = Wv + (size_t)row * KTOT;
        uint2* dhi = (uint2*)(g_w_hi + (size_t)row * KPAD);
        uint2* dlo = (uint2*)(g_w_lo + (size_t)row * KPAD);
        for (int k4 = tid; k4 < KPAD / 4; k4 += 256) {
            int k = k4 * 4;
            uint2 hi, lo;
            if (k < KTOT) {
                float4 v = *(const float4*)(src + k);
                __half2 h0 = __floats2half2_rn(v.x, v.y);
                __half2 h1 = __floats2half2_rn(v.z, v.w);
                float2 f0 = __half22float2(h0);
                float2 f1 = __half22float2(h1);
                __half2 l0 = __floats2half2_rn(v.x - f0.x, v.y - f0.y);
                __half2 l1 = __floats2half2_rn(v.z - f1.x, v.w - f1.y);
                hi = make_uint2(*(uint32_t*)&h0, *(uint32_t*)&h1);
                lo = make_uint2(*(uint32_t*)&l0, *(uint32_t*)&l1);
            } else {
                hi = make_uint2(0, 0);
                lo = make_uint2(0, 0);
            }
            dhi[k4] = hi;
            dlo[k4] = lo;
        }
        return;
    }

    // ---- RoI-align path ----
    __shared__ int   s_off[49][4];
    __shared__ float s_w[49][4];

    const int r = bid;
    const int b = r / SN_;

    if (tid < 49) {
        const float* bb = bboxs + (size_t)r * 4;
        const float sc = 0.0625f;
        float x1 = nan_to_num(bb[0] * sc) - 0.5f;
        float y1 = nan_to_num(bb[1] * sc) - 0.5f;
        float x2 = nan_to_num(bb[2] * sc) - 0.5f;
        float y2 = nan_to_num(bb[3] * sc) - 0.5f;
        float bw = (x2 - x1) * (1.0f / OSZ);
        float bh = (y2 - y1) * (1.0f / OSZ);

        int py = tid / OSZ, px = tid - py * OSZ;
        float y = y1 + ((float)py + 0.5f) * bh;
        float x = x1 + ((float)px + 0.5f) * bw;
        bool valid = (y > -1.0f) && (y < (float)FY) && (x > -1.0f) && (x < (float)FX);
        float yc = fminf(fmaxf(y, 0.0f), (float)(FY - 1));
        float xc = fminf(fmaxf(x, 0.0f), (float)(FX - 1));
        int yl = (int)floorf(yc);
        int xl = (int)floorf(xc);
        int yh = min(yl + 1, FY - 1);
        int xh = min(xl + 1, FX - 1);
        float ly = yc - (float)yl, lx = xc - (float)xl;
        float hy = 1.0f - ly, hx = 1.0f - lx;
        float vm = valid ? 1.0f : 0.0f;

        s_off[tid][0] = yl * FX + xl;
        s_off[tid][1] = yl * FX + xh;
        s_off[tid][2] = yh * FX + xl;
        s_off[tid][3] = yh * FX + xh;
        s_w[tid][0] = hy * hx * vm;
        s_w[tid][1] = hy * lx * vm;
        s_w[tid][2] = ly * hx * vm;
        s_w[tid][3] = ly * lx * vm;
    }
    __syncthreads();

    const float* fbase = zvis + (size_t)b * NCH * TFRM * FY * FX + (size_t)3 * FY * FX;
    __half* ohi = g_pl_hi + (size_t)r * KPAD;
    __half* olo = g_pl_lo + (size_t)r * KPAD;

    for (int k = tid; k < DIN; k += 256) {
        int c = k / 49;
        int p = k - c * 49;
        const float* f = fbase + (size_t)c * (TFRM * FY * FX);
        float v = s_w[p][0] * f[s_off[p][0]]
                + s_w[p][1] * f[s_off[p][1]]
                + s_w[p][2] * f[s_off[p][2]]
                + s_w[p][3] * f[s_off[p][3]];
        __half h = __float2half_rn(v);
        ohi[k] = h;
        olo[k] = __float2half_rn(v - __half2float(h));
    }
    if (tid < (KPAD - DIN)) {
        ohi[DIN + tid] = __float2half_rn(0.0f);
        olo[DIN + tid] = __float2half_rn(0.0f);
    }
}

// ---------------- kernel 2: fp16 three-term HMMA GEMM (split-K 23, 5-stage) ----------------
// acc = Ah*Bh + Al*Bh + Ah*Bl   (drops only Al*Bl ~ 2^-24)
__global__ void __launch_bounds__(256) gemm_hmma(int) {
    extern __shared__ __align__(16) char smem[];

    const int tid   = threadIdx.x;
    const int warp  = tid >> 5;
    const int lane  = tid & 31;
    const int nBase = blockIdx.x * BN;
    const int mBase = blockIdx.y * BM;
    const int z     = blockIdx.z;

    const uint32_t sbase = smem_u32(smem);

    // loader mapping
    const int lrow = tid >> 2;        // 0..63
    const int lseg = tid & 3;         // 16B segment

    // compute mapping
    const int warpM = warp >> 2;      // 0..1 -> *64
    const int warpN = warp & 3;       // 0..3 -> *32
    const uint32_t a_row = (uint32_t)(warpM * 64 + (lane & 15));
    const uint32_t a_seg = (uint32_t)(lane >> 4);
    const uint32_t b_row = (uint32_t)(warpN * 32 + ((lane >> 4) << 3) + (lane & 7));
    const uint32_t b_seg = (uint32_t)((lane >> 3) & 1);

    float acc[4][4][4];
    #pragma unroll
    for (int i = 0; i < 4; ++i)
        #pragma unroll
        for (int j = 0; j < 4; ++j)
            #pragma unroll
            for (int q = 0; q < 4; ++q) acc[i][j][q] = 0.0f;

    auto load_stage = [&](int s, int kt) {
        const int koff = (z * KT_PER + kt) * BK;
        const uint32_t st = sbase + s * STAGE_B;
        const __half* ah0 = g_pl_hi + (size_t)(mBase + lrow)      * KPAD + koff + lseg * 8;
        const __half* ah1 = g_pl_hi + (size_t)(mBase + lrow + 64) * KPAD + koff + lseg * 8;
        const __half* al0 = g_pl_lo + (size_t)(mBase + lrow)      * KPAD + koff + lseg * 8;
        const __half* al1 = g_pl_lo + (size_t)(mBase + lrow + 64) * KPAD + koff + lseg * 8;
        const __half* bh0 = g_w_hi + (size_t)(nBase + lrow)      * KPAD + koff + lseg * 8;
        const __half* bh1 = g_w_hi + (size_t)(nBase + lrow + 64) * KPAD + koff + lseg * 8;
        const __half* bl0 = g_w_lo + (size_t)(nBase + lrow)      * KPAD + koff + lseg * 8;
        const __half* bl1 = g_w_lo + (size_t)(nBase + lrow + 64) * KPAD + koff + lseg * 8;
        cp_async16(st +              lrow * SROW        + lseg * 16, ah0);
        cp_async16(st +             (lrow + 64) * SROW  + lseg * 16, ah1);
        cp_async16(st + SUBT_B     + lrow * SROW        + lseg * 16, al0);
        cp_async16(st + SUBT_B     + (lrow + 64) * SROW + lseg * 16, al1);
        cp_async16(st + 2 * SUBT_B + lrow * SROW        + lseg * 16, bh0);
        cp_async16(st + 2 * SUBT_B + (lrow + 64) * SROW + lseg * 16, bh1);
        cp_async16(st + 3 * SUBT_B + lrow * SROW        + lseg * 16, bl0);
        cp_async16(st + 3 * SUBT_B + (lrow + 64) * SROW + lseg * 16, bl1);
        cp_commit();
    };

    load_stage(0, 0);
    load_stage(1, 1);
    load_stage(2, 2);
    load_stage(3, 3);

    for (int kt = 0; kt < KT_PER; ++kt) {
        cp_wait<3>();
        __syncthreads();
        if (kt + 4 < KT_PER) {
            int s = kt + 4;
            s = (s >= NSTAGE) ? (s - NSTAGE) : s;
            if (kt + 4 >= 2 * NSTAGE) s = (kt + 4) % NSTAGE;
            load_stage((kt + 4) % NSTAGE, kt + 4);
        }

        const uint32_t st  = sbase + (kt % NSTAGE) * STAGE_B;
        const uint32_t sah = st;
        const uint32_t sal = st + SUBT_B;
        const uint32_t sbh = st + 2 * SUBT_B;
        const uint32_t sbl = st + 3 * SUBT_B;

        #pragma unroll
        for (int ks = 0; ks < 2; ++ks) {
            uint32_t bh[2][4], bl[2][4];
            #pragma unroll
            for (int pr = 0; pr < 2; ++pr) {
                ldsm_x4(bh[pr], sbh + (b_row + pr * 16) * SROW + (ks * 2 + b_seg) * 16);
                ldsm_x4(bl[pr], sbl + (b_row + pr * 16) * SROW + (ks * 2 + b_seg) * 16);
            }

            uint32_t ah[4][4], al[4][4];
            #pragma unroll
            for (int mf = 0; mf < 4; ++mf) {
                ldsm_x4(ah[mf], sah + (a_row + mf * 16) * SROW + (ks * 2 + a_seg) * 16);
                ldsm_x4(al[mf], sal + (a_row + mf * 16) * SROW + (ks * 2 + a_seg) * 16);
            }

            #pragma unroll
            for (int mf = 0; mf < 4; ++mf)
                #pragma unroll
                for (int nf = 0; nf < 4; ++nf)
                    mma_f16(acc[mf][nf], ah[mf], bh[nf >> 1][(nf & 1) * 2], bh[nf >> 1][(nf & 1) * 2 + 1]);
            #pragma unroll
            for (int mf = 0; mf < 4; ++mf)
                #pragma unroll
                for (int nf = 0; nf < 4; ++nf)
                    mma_f16(acc[mf][nf], al[mf], bh[nf >> 1][(nf & 1) * 2], bh[nf >> 1][(nf & 1) * 2 + 1]);
            #pragma unroll
            for (int mf = 0; mf < 4; ++mf)
                #pragma unroll
                for (int nf = 0; nf < 4; ++nf)
                    mma_f16(acc[mf][nf], ah[mf], bl[nf >> 1][(nf & 1) * 2], bl[nf >> 1][(nf & 1) * 2 + 1]);
        }
    }

    // epilogue -> g_partial[z][m][n]
    const int group = lane >> 2;
    const int quad  = lane & 3;
    #pragma unroll
    for (int mf = 0; mf < 4; ++mf) {
        int row0 = mBase + warpM * 64 + mf * 16 + group;
        #pragma unroll
        for (int nf = 0; nf < 4; ++nf) {
            int col = nBase + warpN * 32 + nf * 8 + quad * 2;
            float* p0 = g_partial + ((size_t)z * NROI + row0) * NDF + col;
            float* p1 = p0 + (size_t)8 * NDF;
            *(float2*)p0 = make_float2(acc[mf][nf][0], acc[mf][nf][1]);
            *(float2*)p1 = make_float2(acc[mf][nf][2], acc[mf][nf][3]);
        }
    }
}

// ---------------- kernel 3: fused reduce + bias + cluster (4 rois/block) ----------------
__global__ void cluster_fused_kernel(const float* __restrict__ norms,
                                     const float* __restrict__ b_vis,
                                     const float* __restrict__ w_spc,
                                     const float* __restrict__ b_spc,
                                     const float* __restrict__ cent,
                                     float* __restrict__ Z,
                                     float* __restrict__ out_s,
                                     float* __restrict__ out_c) {
    __shared__ __align__(16) float zrow[4][NDF];
    __shared__ float sdist[4][NCLUS];
    __shared__ float ssum[4];
    __shared__ int   sarg[4];

    const int m0  = blockIdx.x * 4;
    const int tid = threadIdx.x;
    float nm[4];
    #pragma unroll
    for (int j = 0; j < 4; ++j) nm[j] = norms[m0 + j];

    for (int d = tid; d < NDF; d += 256) {
        float base = b_vis[d] + b_spc[d];
        float w = w_spc[d];
        float a[4];
        #pragma unroll
        for (int j = 0; j < 4; ++j) a[j] = base + nm[j] * w;
        for (int zz = 0; zz < SPLITK; ++zz) {
            const float* pp = g_partial + ((size_t)zz * NROI + m0) * NDF + d;
            #pragma unroll
            for (int j = 0; j < 4; ++j) a[j] += pp[(size_t)j * NDF];
        }
        #pragma unroll
        for (int j = 0; j < 4; ++j) {
            zrow[j][d] = a[j];
            Z[(size_t)(m0 + j) * NDF + d] = a[j];
        }
    }
    __syncthreads();

    const int warp = tid >> 5;
    const int lane = tid & 31;
    for (int k = warp; k < NCLUS; k += 8) {
        const float4* ck = (const float4*)(cent + (size_t)k * NDF);
        float s[4] = {0.f, 0.f, 0.f, 0.f};
        #pragma unroll
        for (int i = 0; i < 8; ++i) {
            int d4 = i * 32 + lane;
            float4 c = ck[d4];
            #pragma unroll
            for (int j = 0; j < 4; ++j) {
                float4 zv = *(const float4*)&zrow[j][d4 * 4];
                float t;
                t = zv.x - c.x; s[j] += t * t;
                t = zv.y - c.y; s[j] += t * t;
                t = zv.z - c.z; s[j] += t * t;
                t = zv.w - c.w; s[j] += t * t;
            }
        }
        #pragma unroll
        for (int o = 16; o; o >>= 1)
            #pragma unroll
            for (int j = 0; j < 4; ++j)
                s[j] += __shfl_xor_sync(0xffffffffu, s[j], o);
        if (lane == 0)
            #pragma unroll
            for (int j = 0; j < 4; ++j) sdist[j][k] = sqrtf(s[j]);
    }
    __syncthreads();

    if (tid < 4) {
        float sum = 0.0f, best = -1.0f;
        int bi = 0;
        for (int k = 0; k < NCLUS; ++k) {
            float st = 1.0f / (1.0f + sdist[tid][k]);
            sum += st;
            if (st > best) { best = st; bi = k; }
        }
        ssum[tid] = sum;
        sarg[tid] = bi;
    }
    __syncthreads();

    {
        const int j = tid >> 6;          // 0..3
        const int kk = tid & 63;         // 0..63
        if (kk < NCLUS)
            out_s[(size_t)(m0 + j) * NCLUS + kk] = (1.0f / (1.0f + sdist[j][kk])) / ssum[j];
    }
    if (tid < 4) out_c[m0 + tid] = (float)sarg[tid];
}

// ---------------- launch ----------------
extern "C" void kernel_launch(void* const* d_in, const int* in_sizes, int n_in,
                              void* d_out, int out_size) {
    const float* z_vis     = (const float*)d_in[0];
    const float* bboxs     = (const float*)d_in[1];
    const float* norms     = (const float*)d_in[2];
    const float* w_vis     = (const float*)d_in[3];
    const float* b_vis     = (const float*)d_in[4];
    const float* w_spc     = (const float*)d_in[5];
    const float* b_spc     = (const float*)d_in[6];
    const float* centroids = (const float*)d_in[7];

    float* out = (float*)d_out;
    float* Z = out;
    float* S = out + (size_t)NROI * NDF;
    float* C = S + (size_t)NROI * NCLUS;

    cudaFuncSetAttribute(gemm_hmma, cudaFuncAttributeMaxDynamicSharedMemorySize, SMEM_DYN);

    producers_kernel<<<NROI + NDF, 256>>>(z_vis, bboxs, w_vis);

    dim3 gg(NDF / BN, NROI / BM, SPLITK);        // (8, 4, 23) = 736 CTAs
    gemm_hmma<<<gg, 256, SMEM_DYN>>>(0);

    cluster_fused_kernel<<<NROI / 4, 256>>>(norms, b_vis, w_spc, b_spc, centroids, Z, S, C);
}